// round 1
// baseline (speedup 1.0000x reference)
#include <cuda_runtime.h>

#define N_NODES 50000
#define N_EDGES 600000
#define N_TOT   (N_NODES + N_EDGES)
#define N_GRAPHS 256
#define D 128
#define NLAYER 4
#define BN_EPS 1e-5f

// ---------------- scratch (device globals; no dynamic alloc allowed) ----------------
__device__ float g_h[(size_t)N_NODES * D];     // h, then z (in-place), then h again
__device__ float g_aggr[(size_t)N_NODES * D];
__device__ float g_Wt[D * D];                  // transposed layer weight
__device__ float g_ct[243 * D];                // combo bond-embedding table
__device__ float g_stats[2 * D];               // colsum, colsumsq
__device__ float g_scale[D];
__device__ float g_shift[D];
__device__ float g_pool[N_GRAPHS * D];
__device__ int   g_off[N_NODES + 1];
__device__ int   g_cur[N_NODES];
__device__ int   g_adj[N_TOT];                 // packed: src | (combo<<16)
__device__ int   g_bsums[64];
__device__ int   g_bounds[N_GRAPHS + 1];

// ---------------- atom embedding: h[i,d] = sum_f atom_emb[f, x[i,f], d] ----------------
__global__ void k_atom(const int* __restrict__ x, const float* __restrict__ aemb) {
    int i = blockIdx.x, t = threadIdx.x;
    const int* xi = x + (size_t)i * 9;
    float acc = 0.f;
#pragma unroll
    for (int f = 0; f < 9; f++) {
        int v = xi[f];
        acc += __ldg(&aemb[((size_t)f * 120 + v) * D + t]);
    }
    g_h[(size_t)i * D + t] = acc;
}

// ---------------- CSR build ----------------
__global__ void k_initdeg() {
    int i = blockIdx.x * blockDim.x + threadIdx.x;
    if (i < N_NODES) g_off[i] = 1;   // self-loop
}

__global__ void k_hist(const int* __restrict__ e_dst) {
    int e = blockIdx.x * blockDim.x + threadIdx.x;
    if (e < N_EDGES) atomicAdd(&g_off[e_dst[e]], 1);
}

__global__ void k_scan1() {
    __shared__ int sh[1024];
    int t = threadIdx.x;
    int idx = blockIdx.x * 1024 + t;
    int v = (idx < N_NODES) ? g_off[idx] : 0;
    sh[t] = v;
    __syncthreads();
    for (int off = 1; off < 1024; off <<= 1) {
        int xv = (t >= off) ? sh[t - off] : 0;
        __syncthreads();
        sh[t] += xv;
        __syncthreads();
    }
    if (idx < N_NODES) g_off[idx] = sh[t] - v;  // block-local exclusive
    if (t == 1023) g_bsums[blockIdx.x] = sh[1023];
}

__global__ void k_scan2(int nblk) {
    if (threadIdx.x == 0) {
        int run = 0;
        for (int i = 0; i < nblk; i++) { int tmp = g_bsums[i]; g_bsums[i] = run; run += tmp; }
    }
}

__global__ void k_scan3() {
    int i = blockIdx.x * blockDim.x + threadIdx.x;
    if (i < N_NODES) {
        int o = g_off[i] + g_bsums[i >> 10];
        g_off[i] = o;
        g_cur[i] = o;
    }
    if (i == 0) g_off[N_NODES] = N_TOT;
}

__global__ void k_scatter(const int* __restrict__ e_src, const int* __restrict__ e_dst,
                          const int* __restrict__ ea) {
    int t = blockIdx.x * blockDim.x + threadIdx.x;
    if (t >= N_TOT) return;
    int d, s, comb;
    if (t < N_EDGES) {
        s = e_src[t];
        d = e_dst[t];
        const int* a = ea + (size_t)t * 5;
        comb = a[0] + 3 * a[1] + 9 * a[2] + 27 * a[3] + 81 * a[4];
    } else {
        d = s = t - N_EDGES;   // self loop; edge_attr zeros -> combo 0
        comb = 0;
    }
    int pos = atomicAdd(&g_cur[d], 1);
    g_adj[pos] = s | (comb << 16);
}

// ---------------- per-layer: combo bond table (+ zero stats) ----------------
__global__ void k_ct(const float* __restrict__ bemb /* layer base [5][7][D] */) {
    int c = blockIdx.x, t = threadIdx.x;
    int cc = c;
    float acc = 0.f;
#pragma unroll
    for (int f = 0; f < 5; f++) {
        int dig = cc % 3; cc /= 3;
        acc += __ldg(&bemb[(f * 7 + dig) * D + t]);
    }
    g_ct[c * D + t] = acc;
    if (c == 0) { g_stats[t] = 0.f; g_stats[D + t] = 0.f; }
}

// ---------------- per-layer: transpose W ----------------
__global__ void k_wt(const float* __restrict__ W) {
    int idx = blockIdx.x * blockDim.x + threadIdx.x;
    if (idx < D * D) {
        int c = idx >> 7, k = idx & 127;
        g_Wt[k * D + c] = W[idx];   // W[c][k]
    }
}

// ---------------- aggregation: aggr[i,:] = sum_e (h[src_e,:] + ct[comb_e,:]) ----------------
__global__ void k_aggr() {
    int i = blockIdx.x, t = threadIdx.x;
    int s = g_off[i], e = g_off[i + 1];
    __shared__ int sp[64];
    float acc = 0.f;
    for (int base = s; base < e; base += 64) {
        int cnt = min(64, e - base);
        if (t < cnt) sp[t] = g_adj[base + t];
        __syncthreads();
#pragma unroll 4
        for (int j = 0; j < cnt; j++) {
            int p = sp[j];
            acc += g_h[(size_t)(p & 0xFFFF) * D + t] + g_ct[(p >> 16) * D + t];
        }
        __syncthreads();
    }
    g_aggr[(size_t)i * D + t] = acc;
}

// ---------------- GEMM (z = aggr @ W^T + b) + column stats, z -> g_h ----------------
__global__ void k_gemm(const float* __restrict__ lin_b) {
    __shared__ float As[64 * D];   // 32KB
    int t = threadIdx.x;
    int tx = t & 31, ty = t >> 5;
    int row0 = blockIdx.x * 64;

    const float4* src4 = (const float4*)g_aggr;
    float4* dst4 = (float4*)As;
    for (int i = t; i < 64 * 32; i += 256) {
        int r = i >> 5;
        int gr = row0 + r;
        float4 v = (gr < N_NODES) ? src4[(size_t)gr * 32 + (i & 31)] : make_float4(0.f, 0.f, 0.f, 0.f);
        dst4[i] = v;
    }
    __syncthreads();

    int c0 = tx * 4;
    float acc[8][4];
#pragma unroll
    for (int rr = 0; rr < 8; rr++) { acc[rr][0] = acc[rr][1] = acc[rr][2] = acc[rr][3] = 0.f; }

    const float* As_base = As + (ty * 8) * D;
#pragma unroll 4
    for (int k = 0; k < D; k++) {
        float4 w = __ldg((const float4*)(g_Wt + k * D + c0));
#pragma unroll
        for (int rr = 0; rr < 8; rr++) {
            float a = As_base[rr * D + k];
            acc[rr][0] += a * w.x;
            acc[rr][1] += a * w.y;
            acc[rr][2] += a * w.z;
            acc[rr][3] += a * w.w;
        }
    }

    float4 b = *(const float4*)(lin_b + c0);
    float ps[4] = {0.f, 0.f, 0.f, 0.f};
    float pq[4] = {0.f, 0.f, 0.f, 0.f};
#pragma unroll
    for (int rr = 0; rr < 8; rr++) {
        int gr = row0 + ty * 8 + rr;
        if (gr < N_NODES) {
            float z0 = acc[rr][0] + b.x, z1 = acc[rr][1] + b.y;
            float z2 = acc[rr][2] + b.z, z3 = acc[rr][3] + b.w;
            ((float4*)g_h)[(size_t)gr * 32 + tx] = make_float4(z0, z1, z2, z3);
            ps[0] += z0; ps[1] += z1; ps[2] += z2; ps[3] += z3;
            pq[0] += z0 * z0; pq[1] += z1 * z1; pq[2] += z2 * z2; pq[3] += z3 * z3;
        }
    }

    __syncthreads();
    float* red = As;   // reuse: [8][128] sums + [8][128] sumsq = 8KB
#pragma unroll
    for (int j = 0; j < 4; j++) {
        red[ty * D + c0 + j] = ps[j];
        red[1024 + ty * D + c0 + j] = pq[j];
    }
    __syncthreads();
    if (ty == 0) {
#pragma unroll
        for (int j = 0; j < 4; j++) {
            float s = 0.f, q = 0.f;
#pragma unroll
            for (int w2 = 0; w2 < 8; w2++) {
                s += red[w2 * D + c0 + j];
                q += red[1024 + w2 * D + c0 + j];
            }
            atomicAdd(&g_stats[c0 + j], s);
            atomicAdd(&g_stats[D + c0 + j], q);
        }
    }
}

// ---------------- BN finalize ----------------
__global__ void k_bnfin(const float* __restrict__ gamma, const float* __restrict__ beta) {
    int t = threadIdx.x;
    float mu = g_stats[t] / (float)N_NODES;
    float var = g_stats[D + t] / (float)N_NODES - mu * mu;
    float rstd = rsqrtf(fmaxf(var, 0.f) + BN_EPS);
    float sc = rstd * gamma[t];
    g_scale[t] = sc;
    g_shift[t] = beta[t] - mu * sc;
}

// ---------------- BN apply + ReLU (in place on g_h) ----------------
__global__ void k_bnapply() {
    int idx = blockIdx.x * blockDim.x + threadIdx.x;
    if (idx >= N_NODES * 32) return;
    int c4 = idx & 31;
    float4 z = ((float4*)g_h)[idx];
    float4 sc = ((const float4*)g_scale)[c4];
    float4 sh = ((const float4*)g_shift)[c4];
    z.x = fmaxf(z.x * sc.x + sh.x, 0.f);
    z.y = fmaxf(z.y * sc.y + sh.y, 0.f);
    z.z = fmaxf(z.z * sc.z + sh.z, 0.f);
    z.w = fmaxf(z.w * sc.w + sh.w, 0.f);
    ((float4*)g_h)[idx] = z;
}

// ---------------- pooling ----------------
__global__ void k_bounds(const int* __restrict__ batch) {
    int t = threadIdx.x;
    if (t <= N_GRAPHS) {
        int lo = 0, hi = N_NODES;
        while (lo < hi) {
            int mid = (lo + hi) >> 1;
            if (batch[mid] < t) lo = mid + 1; else hi = mid;
        }
        g_bounds[t] = lo;
    }
}

__global__ void k_pool() {
    int g = blockIdx.x, t = threadIdx.x;
    int lo = g_bounds[g], hi = g_bounds[g + 1];
    float s = 0.f;
    for (int r = lo; r < hi; r++) s += g_h[(size_t)r * D + t];
    int cnt = hi - lo;
    g_pool[g * D + t] = s / (float)max(cnt, 1);
}

// ---------------- MLP head ----------------
__global__ void k_mlp(const float* __restrict__ w1, const float* __restrict__ b1,
                      const float* __restrict__ w2, const float* __restrict__ b2,
                      float* __restrict__ out) {
    int g = blockIdx.x, j = threadIdx.x;   // 64 threads
    const float* gp = g_pool + g * D;
    const float* wr = w1 + j * D;
    float a = b1[j];
#pragma unroll 4
    for (int k = 0; k < D; k++) a += gp[k] * wr[k];
    a = fmaxf(a, 0.f);
    float v = a * w2[j];
#pragma unroll
    for (int o = 16; o > 0; o >>= 1) v += __shfl_down_sync(0xFFFFFFFFu, v, o);
    __shared__ float sh[2];
    if ((j & 31) == 0) sh[j >> 5] = v;
    __syncthreads();
    if (j == 0) out[g] = sh[0] + sh[1] + b2[0];
}

// ---------------- launch ----------------
extern "C" void kernel_launch(void* const* d_in, const int* in_sizes, int n_in,
                              void* d_out, int out_size) {
    const int*   x        = (const int*)d_in[0];
    const int*   ei       = (const int*)d_in[1];
    const int*   ea       = (const int*)d_in[2];
    const int*   batch    = (const int*)d_in[3];
    const float* atom_emb = (const float*)d_in[4];
    const float* bond_emb = (const float*)d_in[5];
    const float* lin_w    = (const float*)d_in[6];
    const float* lin_b    = (const float*)d_in[7];
    const float* bn_g     = (const float*)d_in[8];
    const float* bn_b     = (const float*)d_in[9];
    const float* w1       = (const float*)d_in[10];
    const float* b1       = (const float*)d_in[11];
    const float* w2       = (const float*)d_in[12];
    const float* b2       = (const float*)d_in[13];
    float* out = (float*)d_out;

    const int* e_src = ei;
    const int* e_dst = ei + N_EDGES;

    k_atom<<<N_NODES, D>>>(x, atom_emb);
    k_initdeg<<<(N_NODES + 255) / 256, 256>>>();
    k_hist<<<(N_EDGES + 255) / 256, 256>>>(e_dst);
    const int SCAN_BLOCKS = (N_NODES + 1023) / 1024;   // 49
    k_scan1<<<SCAN_BLOCKS, 1024>>>();
    k_scan2<<<1, 32>>>(SCAN_BLOCKS);
    k_scan3<<<(N_NODES + 255) / 256, 256>>>();
    k_scatter<<<(N_TOT + 255) / 256, 256>>>(e_src, e_dst, ea);

    for (int l = 0; l < NLAYER; l++) {
        k_ct<<<243, D>>>(bond_emb + (size_t)l * 5 * 7 * D);
        k_wt<<<(D * D + 255) / 256, 256>>>(lin_w + (size_t)l * D * D);
        k_aggr<<<N_NODES, D>>>();
        k_gemm<<<(N_NODES + 63) / 64, 256>>>(lin_b + l * D);
        k_bnfin<<<1, D>>>(bn_g + l * D, bn_b + l * D);
        k_bnapply<<<(N_NODES * 32 + 255) / 256, 256>>>();
    }

    k_bounds<<<1, 512>>>(batch);
    k_pool<<<N_GRAPHS, D>>>();
    k_mlp<<<N_GRAPHS, 64>>>(w1, b1, w2, b2, out);
}